// round 13
// baseline (speedup 1.0000x reference)
#include <cuda_runtime.h>
#include <cuda_fp16.h>
#include <cstdint>

// B=128, U=64, A=64. fp16 mma.sync m16n8k16, single plane.
// X layout: [u][k-pair] u32 rows (k contiguous) -> B operands via ldmatrix.x4.
// CTA = 2 independent 128-thread halves; persistent; cp.async double-buffered.

#define NBA 8192

__device__ __align__(16) uint32_t g_cgP4[NBA * 64 * 4];          // [ba][u][4] (16B/u)
__device__ __align__(16) uint32_t g_rP[(size_t)NBA * 2048];      // [ba][u*32+c2]
__device__ __align__(16) uint32_t g_msgsP[(size_t)NBA * 2048];
__device__ float g_sums[128 * 4096];
__device__ float g_P[128 * 4096];
__device__ __align__(16) uint32_t g_wfrag[48128];

#define OFF_PHI1_W1F 0
#define OFF_PHI1_W2F 512
#define OFF_PHIK_W1F 2560
#define OFF_PHIK_W2F 12800
#define OFF_G1_W1F   20992
#define OFF_G1_W2F   23552
#define OFF_GK_W1F   25600
#define OFF_GK_W2F   37888
#define OFF_G5_W1F   44032

#define CP_ASYNC16(dst, src) asm volatile("cp.async.cg.shared.global [%0], [%1], 16;" :: "r"(dst), "l"(src))
#define CP_COMMIT()          asm volatile("cp.async.commit_group;" ::: "memory")
#define CP_WAIT1()           asm volatile("cp.async.wait_group 1;" ::: "memory")
#define BARH(id)             asm volatile("bar.sync %0, 128;" :: "r"(id) : "memory")
#define LDM4(r0, r1, r2, r3, a) asm volatile( \
    "ldmatrix.sync.aligned.m8n8.x4.shared.b16 {%0,%1,%2,%3}, [%4];" \
    : "=r"(r0), "=r"(r1), "=r"(r2), "=r"(r3) : "r"(a))

__device__ __forceinline__ uint32_t packh(float lo, float hi) {
    return (uint32_t)__half_as_ushort(__float2half_rn(lo)) |
           ((uint32_t)__half_as_ushort(__float2half_rn(hi)) << 16);
}
__device__ __forceinline__ void mma16816(float d[4], const uint4& a, uint32_t b0, uint32_t b1) {
    asm volatile("mma.sync.aligned.m16n8k16.row.col.f32.f16.f16.f32 "
                 "{%0,%1,%2,%3}, {%4,%5,%6,%7}, {%8,%9}, {%0,%1,%2,%3};\n"
                 : "+f"(d[0]), "+f"(d[1]), "+f"(d[2]), "+f"(d[3])
                 : "r"(a.x), "r"(a.y), "r"(a.z), "r"(a.w), "r"(b0), "r"(b1));
}

// ---------------- prep: fp16 A-fragments (verified; unchanged) ---------------
__global__ void prep_kernel(const float* __restrict__ phi1W1, const float* __restrict__ phi1W2,
                            const float* __restrict__ phiKW1, const float* __restrict__ phiKW2,
                            const float* __restrict__ g1W1,   const float* __restrict__ g1W2,
                            const float* __restrict__ gKW1,   const float* __restrict__ gKW2,
                            const float* __restrict__ g5W1) {
    const int id = blockIdx.x;
    const float* src; int off, KB, type;
    if (id == 0)       { src = phi1W1;              off = OFF_PHI1_W1F;            KB = 1; type = 3; }
    else if (id == 1)  { src = phi1W2;              off = OFF_PHI1_W2F;            KB = 4; type = 0; }
    else if (id < 6)   { int i = id - 2;  src = phiKW1 + i * 64 * 65;  off = OFF_PHIK_W1F + i * 2560; KB = 5; type = 1; }
    else if (id < 10)  { int i = id - 6;  src = phiKW2 + i * 4096;     off = OFF_PHIK_W2F + i * 2048; KB = 4; type = 0; }
    else if (id == 10) { src = g1W1;                off = OFF_G1_W1F;              KB = 5; type = 4; }
    else if (id == 11) { src = g1W2;                off = OFF_G1_W2F;              KB = 4; type = 0; }
    else if (id < 15)  { int i = id - 12; src = gKW1 + i * 64 * 128;   off = OFF_GK_W1F + i * 4096;   KB = 8; type = 5; }
    else if (id < 18)  { int i = id - 15; src = gKW2 + i * 4096;       off = OFF_GK_W2F + i * 2048;   KB = 4; type = 0; }
    else               { src = g5W1;                off = OFF_G5_W1F;              KB = 8; type = 5; }

    const float ninv = -1.0f / 63.0f;
    const int total = KB * 512;
    for (int e = threadIdx.x; e < total; e += blockDim.x) {
        int strip = e / (KB * 128);
        int rem   = e % (KB * 128);
        int kt = rem / 128;
        int r3 = rem & 127;
        int lane = r3 >> 2, j = r3 & 3;
        int o  = strip * 16 + (lane >> 2) + 8 * (j & 1);
        int k0 = kt * 16 + (lane & 3) * 2 + 8 * (j >> 1);
        float w0, w1;
        if (type == 0)      { w0 = src[o * 64 + k0];  w1 = src[o * 64 + k0 + 1]; }
        else if (type == 5) { w0 = src[o * 128 + k0]; w1 = src[o * 128 + k0 + 1];
                              if (k0 >= 64) { w0 *= ninv; w1 *= ninv; } }
        else if (type == 1 || type == 4) {
            auto fetch = [&](int c) -> float {
                if (c < 64) { float v = src[o * 65 + 1 + c]; return (type == 4) ? v * ninv : v; }
                if (c == 64) return src[o * 65];
                return 0.0f;
            };
            w0 = fetch(k0); w1 = fetch(k0 + 1);
        } else {
            w0 = (k0 == 0) ? (src[o * 2] + src[o * 2 + 1]) : 0.0f;
            w1 = 0.0f;
        }
        g_wfrag[off + e] = packh(w0, w1);
    }
}

__global__ void cgt_kernel(const float* __restrict__ cg) {
    const int b = blockIdx.x;
    for (int j = threadIdx.x; j < 4096; j += 256) {
        int a = j >> 6, u = j & 63;
        uint32_t* d = g_cgP4 + ((size_t)(b * 64 + a) * 64 + u) * 4;
        d[0] = packh(cg[b * 4096 + u * 64 + a], 0.0f);
        d[1] = 0; d[2] = 0; d[3] = 0;
    }
}

__global__ void asum_kernel() {
    const int b = blockIdx.x >> 3;
    const int e = (blockIdx.x & 7) * 256 + threadIdx.x;   // u*32 + c2
    const uint32_t* p0 = g_msgsP + (size_t)b * 131072 + e;
    float s0 = 0.f, s1 = 0.f;
#pragma unroll 8
    for (int a = 0; a < 64; ++a) {
        uint32_t h = p0[(size_t)a * 2048];
        __half2 hv = *reinterpret_cast<const __half2*>(&h);
        float2 f = __half22float2(hv);
        s0 += f.x; s1 += f.y;
    }
    int u = e >> 5, c2 = e & 31;
    g_sums[b * 4096 + (2 * c2) * 64 + u]     = s0;
    g_sums[b * 4096 + (2 * c2 + 1) * 64 + u] = s1;
}

__global__ void pP_kernel(const float* __restrict__ Wsrc, const float* __restrict__ b1,
                          int CW, int cOff) {
    __shared__ float sWT[64 * 65];
    __shared__ float sS2[4096];
    const int b = blockIdx.x, t = threadIdx.x;
    for (int idx = t; idx < 4096; idx += 256) {
        int o = idx >> 6, c = idx & 63;
        sWT[c * 65 + o] = Wsrc[o * CW + cOff + c] * (1.0f / 63.0f);
        sS2[idx] = g_sums[b * 4096 + idx];
    }
    __syncthreads();
    const int o = t & 63, ublk = t >> 6;
    float acc[16];
    float bv = __ldg(b1 + o);
#pragma unroll
    for (int i = 0; i < 16; ++i) acc[i] = bv;
    const float4* S4 = (const float4*)sS2;
#pragma unroll 4
    for (int c = 0; c < 64; ++c) {
        float w = sWT[c * 65 + o];
#pragma unroll
        for (int i = 0; i < 4; ++i) {
            float4 s = S4[c * 16 + ublk * 4 + i];
            acc[i * 4 + 0] += w * s.x; acc[i * 4 + 1] += w * s.y;
            acc[i * 4 + 2] += w * s.z; acc[i * 4 + 3] += w * s.w;
        }
    }
    float4* P4 = (float4*)(g_P + b * 4096 + o * 64 + ublk * 16);
#pragma unroll
    for (int i = 0; i < 4; ++i)
        P4[i] = make_float4(acc[i * 4], acc[i * 4 + 1], acc[i * 4 + 2], acc[i * 4 + 3]);
}

// ---------------- cp.async prefetch: rows [u][kpair], stride S1 ---------------
template<int MODE, int S1>
__device__ __forceinline__ void prefetch_slice(uint32_t dstB, int ba, int t2) {
    const uint32_t* rP = g_rP + (size_t)ba * 2048;
    const uint32_t* mP = g_msgsP + (size_t)ba * 2048;
    const uint32_t* cg4 = g_cgP4 + (size_t)ba * 256;
    if (MODE == 0) {
        for (int row = t2; row < 64; row += 128)
            CP_ASYNC16(dstB + (uint32_t)(row * S1) * 4u, cg4 + row * 4);
    } else if (MODE == 3) {
        for (int cc = t2; cc < 64 * 16; cc += 128) {
            int row = cc >> 4, ch = cc & 15;
            const uint32_t* src = (ch < 8) ? (rP + row * 32 + ch * 4)
                                           : (mP + row * 32 + (ch - 8) * 4);
            CP_ASYNC16(dstB + (uint32_t)(row * S1 + ch * 4) * 4u, src);
        }
    } else {
        const uint32_t* base = (MODE == 1) ? rP : mP;
        for (int cc = t2; cc < 64 * 9; cc += 128) {
            int row = cc / 9, ch = cc % 9;
            const uint32_t* src = (ch < 8) ? (base + row * 32 + ch * 4) : (cg4 + row * 4);
            CP_ASYNC16(dstB + (uint32_t)(row * S1 + ch * 4) * 4u, src);
        }
    }
}

// ---------------- layer kernel: 2 halves, ldmatrix B-operands -----------------
// MODE: 0 phi1, 1 phiK, 2 gamma1, 3 gammaK/gamma5
template<int KB1, int MODE, bool FINAL>
__global__ void __launch_bounds__(256, 2) layer_kernel(const float* __restrict__ b1v,
                                                       const float* __restrict__ b2v,
                                                       int w1off, int w2off,
                                                       const float* __restrict__ w2raw,
                                                       float* __restrict__ dout) {
    constexpr bool RELU2 = (MODE >= 2);
    constexpr int S1 = KB1 * 8 + 4;
    constexpr int BUFU = 64 * S1;
    extern __shared__ uint32_t sm[];
    uint32_t* sW1f = sm;                         // KB1*512
    uint32_t* sX   = sW1f + KB1 * 512;           // 4*BUFU
    uint32_t* sH   = sX + 4 * BUFU;              // 2*2304 (!FINAL)
    float*    sRed = (float*)sH;                 // 512 (FINAL)

    const int t = threadIdx.x;
    const int warp = t >> 5, lane = t & 31, q = lane & 3, g = lane >> 2;
    const int half = warp >> 2, wl = warp & 3;
    const int t2 = t & 127;
    const int o_r = wl * 16 + g, o_r8 = o_r + 8;
    const bool geven = ((g & 1) == 0);
    const float inv = 1.0f / 63.0f;
    const int barid = 1 + half;
    const int row_lane = (lane & 7) + ((lane >> 4) << 3);
    const int kb_off = ((lane >> 3) & 1) * 4;

    uint32_t smbase;
    asm("{ .reg .u64 tmp; cvta.to.shared.u64 tmp, %1; cvt.u32.u64 %0, tmp; }"
        : "=r"(smbase) : "l"(sm));
    const uint32_t xbyte = smbase + (uint32_t)(KB1 * 512) * 4u;
    const uint32_t hbyte = smbase + (uint32_t)(KB1 * 512 + 4 * BUFU + half * 2304) * 4u;
    uint32_t* sHh = sH + half * 2304;

    {
        const uint4* gw1 = (const uint4*)(g_wfrag + w1off);
        uint4* d1 = (uint4*)sW1f;
        for (int i = t; i < KB1 * 128; i += 256) d1[i] = gw1[i];
    }
    uint4 W2r[4];
    if (!FINAL) {
        const uint4* gw2 = (const uint4*)(g_wfrag + w2off);
#pragma unroll
        for (int kt = 0; kt < 4; ++kt) W2r[kt] = gw2[wl * 128 + kt * 32 + lane];
    }
    float bA1 = 0.f, bB1 = 0.f, bA2 = 0.f, bB2 = 0.f, w2a = 0.f, w2b = 0.f, bF = 0.f;
    if (MODE < 2) { bA1 = __ldg(b1v + o_r); bB1 = __ldg(b1v + o_r8); }
    if (!FINAL)   { bA2 = __ldg(b2v + o_r); bB2 = __ldg(b2v + o_r8); }
    if (FINAL)    { w2a = __ldg(w2raw + o_r); w2b = __ldg(w2raw + o_r8); bF = __ldg(b2v); }

    {
        int tot = 4 * BUFU + (FINAL ? 512 : 2 * 2304);
        for (int i = t; i < tot; i += 256) sX[i] = 0;
    }
    __syncthreads();

    const int stride2 = gridDim.x * 2;
    const int stream = blockIdx.x * 2 + half;
    int o = 0;
    if (stream < NBA)
        prefetch_slice<MODE, S1>(xbyte + (uint32_t)((half * 2) * BUFU) * 4u, stream, t2);
    CP_COMMIT();

    // ldmatrix base addresses (per n-octet-pair), H base addresses
    uint32_t xadr0[4], hadr0[4];
#pragma unroll
    for (int ntp = 0; ntp < 4; ++ntp) {
        xadr0[ntp] = (uint32_t)(((ntp * 16 + row_lane) * S1 + kb_off) * 4);
        hadr0[ntp] = hbyte + (uint32_t)(((ntp * 16 + row_lane) * 36 + kb_off) * 4);
    }

    for (int ba = stream; ba < NBA; ba += stride2) {
        const int b = ba >> 6;
        int nxt = ba + stride2;
        if (nxt < NBA)
            prefetch_slice<MODE, S1>(xbyte + (uint32_t)((half * 2 + (o ^ 1)) * BUFU) * 4u, nxt, t2);
        CP_COMMIT();
        CP_WAIT1();
        BARH(barid);

        const uint32_t bufB = xbyte + (uint32_t)((half * 2 + o) * BUFU) * 4u;

        // ---- conv1 ----
        float acc[8][4];
#pragma unroll
        for (int nt = 0; nt < 8; ++nt)
#pragma unroll
            for (int j = 0; j < 4; ++j) acc[nt][j] = 0.f;
        {
            const uint4* A1 = (const uint4*)sW1f + wl * (KB1 * 32);
#pragma unroll
            for (int kt = 0; kt < KB1; ++kt) {
                uint4 Ah = A1[kt * 32 + lane];
#pragma unroll
                for (int ntp = 0; ntp < 4; ++ntp) {
                    uint32_t b0a, b1a, b0b, b1b;
                    LDM4(b0a, b1a, b0b, b1b, bufB + xadr0[ntp] + kt * 32);
                    mma16816(acc[2 * ntp],     Ah, b0a, b1a);
                    mma16816(acc[2 * ntp + 1], Ah, b0b, b1b);
                }
            }
        }
        if (MODE >= 2) {
            const float* Pb = g_P + b * 4096;
#pragma unroll
            for (int nt = 0; nt < 8; ++nt) {
                int u0 = nt * 8 + q * 2;
                float2 pa = __ldg((const float2*)(Pb + o_r * 64 + u0));
                float2 pb = __ldg((const float2*)(Pb + o_r8 * 64 + u0));
                acc[nt][0] += pa.x; acc[nt][1] += pa.y;
                acc[nt][2] += pb.x; acc[nt][3] += pb.y;
            }
        } else {
#pragma unroll
            for (int nt = 0; nt < 8; ++nt) {
                acc[nt][0] += bA1; acc[nt][1] += bA1;
                acc[nt][2] += bB1; acc[nt][3] += bB1;
            }
        }
#pragma unroll
        for (int nt = 0; nt < 8; ++nt)
#pragma unroll
            for (int j = 0; j < 4; ++j) acc[nt][j] = fmaxf(acc[nt][j], 0.0f);
        float SA = 0.f, SB = 0.f;
#pragma unroll
        for (int nt = 0; nt < 8; ++nt) { SA += acc[nt][0] + acc[nt][1]; SB += acc[nt][2] + acc[nt][3]; }
        SA += __shfl_xor_sync(0xffffffffu, SA, 1); SA += __shfl_xor_sync(0xffffffffu, SA, 2);
        SB += __shfl_xor_sync(0xffffffffu, SB, 1); SB += __shfl_xor_sync(0xffffffffu, SB, 2);

        if (!FINAL) {
            // post + pair-pack into H rows [u][c2]
#pragma unroll
            for (int nt = 0; nt < 8; ++nt) {
                float t0, t1, t2v, t3;
                if (wl >= 2) {
                    t0 = (SA - acc[nt][0]) * inv; t1 = (SA - acc[nt][1]) * inv;
                    t2v = (SB - acc[nt][2]) * inv; t3 = (SB - acc[nt][3]) * inv;
                } else { t0 = acc[nt][0]; t1 = acc[nt][1]; t2v = acc[nt][2]; t3 = acc[nt][3]; }
                float p0 = __shfl_xor_sync(0xffffffffu, t0, 4);
                float p1 = __shfl_xor_sync(0xffffffffu, t1, 4);
                float p2 = __shfl_xor_sync(0xffffffffu, t2v, 4);
                float p3 = __shfl_xor_sync(0xffffffffu, t3, 4);
                float v0a, v0b, v1a, v1b; int c2;
                if (geven) { c2 = o_r >> 1;        v0a = t0; v0b = p0; v1a = t1; v1b = p1; }
                else       { c2 = (o_r8 - 1) >> 1; v0a = p2; v0b = t2v; v1a = p3; v1b = t3; }
                int u0 = nt * 8 + q * 2;
                sHh[u0 * 36 + c2]       = packh(v0a, v0b);
                sHh[(u0 + 1) * 36 + c2] = packh(v1a, v1b);
            }
            BARH(barid);

            // ---- conv2 (KB=4, W2 in regs, H via ldmatrix) ----
            float a2[8][4];
#pragma unroll
            for (int nt = 0; nt < 8; ++nt)
#pragma unroll
                for (int j = 0; j < 4; ++j) a2[nt][j] = 0.f;
#pragma unroll
            for (int kt = 0; kt < 4; ++kt) {
#pragma unroll
                for (int ntp = 0; ntp < 4; ++ntp) {
                    uint32_t b0a, b1a, b0b, b1b;
                    LDM4(b0a, b1a, b0b, b1b, hadr0[ntp] + kt * 32);
                    mma16816(a2[2 * ntp],     W2r[kt], b0a, b1a);
                    mma16816(a2[2 * ntp + 1], W2r[kt], b0b, b1b);
                }
            }
#pragma unroll
            for (int nt = 0; nt < 8; ++nt) {
                a2[nt][0] += bA2; a2[nt][1] += bA2;
                a2[nt][2] += bB2; a2[nt][3] += bB2;
            }
            if (RELU2) {
#pragma unroll
                for (int nt = 0; nt < 8; ++nt)
#pragma unroll
                    for (int j = 0; j < 4; ++j) a2[nt][j] = fmaxf(a2[nt][j], 0.0f);
            }
            float S2A = 0.f, S2B = 0.f;
#pragma unroll
            for (int nt = 0; nt < 8; ++nt) { S2A += a2[nt][0] + a2[nt][1]; S2B += a2[nt][2] + a2[nt][3]; }
            S2A += __shfl_xor_sync(0xffffffffu, S2A, 1); S2A += __shfl_xor_sync(0xffffffffu, S2A, 2);
            S2B += __shfl_xor_sync(0xffffffffu, S2B, 1); S2B += __shfl_xor_sync(0xffffffffu, S2B, 2);

            uint32_t* gout = (RELU2 ? g_rP : g_msgsP) + (size_t)ba * 2048;
#pragma unroll
            for (int nt = 0; nt < 8; ++nt) {
                float t0, t1, t2v, t3;
                if (wl >= 2) {
                    t0 = (S2A - a2[nt][0]) * inv; t1 = (S2A - a2[nt][1]) * inv;
                    t2v = (S2B - a2[nt][2]) * inv; t3 = (S2B - a2[nt][3]) * inv;
                } else { t0 = a2[nt][0]; t1 = a2[nt][1]; t2v = a2[nt][2]; t3 = a2[nt][3]; }
                float p0 = __shfl_xor_sync(0xffffffffu, t0, 4);
                float p1 = __shfl_xor_sync(0xffffffffu, t1, 4);
                float p2 = __shfl_xor_sync(0xffffffffu, t2v, 4);
                float p3 = __shfl_xor_sync(0xffffffffu, t3, 4);
                float v0a, v0b, v1a, v1b; int c2;
                if (geven) { c2 = o_r >> 1;        v0a = t0; v0b = p0; v1a = t1; v1b = p1; }
                else       { c2 = (o_r8 - 1) >> 1; v0a = p2; v0b = t2v; v1a = p3; v1b = t3; }
                int u0 = nt * 8 + q * 2;
                gout[u0 * 32 + c2]       = packh(v0a, v0b);
                gout[(u0 + 1) * 32 + c2] = packh(v1a, v1b);
            }
        } else {
            // FINAL: post in regs, GEMV partial, cross-warp reduce via sRed
#pragma unroll
            for (int nt = 0; nt < 8; ++nt) {
                float f0, f1, f2, f3;
                if (wl >= 2) {
                    f0 = (SA - acc[nt][0]) * inv; f1 = (SA - acc[nt][1]) * inv;
                    f2 = (SB - acc[nt][2]) * inv; f3 = (SB - acc[nt][3]) * inv;
                } else { f0 = acc[nt][0]; f1 = acc[nt][1]; f2 = acc[nt][2]; f3 = acc[nt][3]; }
                float p0 = w2a * f0 + w2b * f2;
                float p1 = w2a * f1 + w2b * f3;
                p0 += __shfl_xor_sync(0xffffffffu, p0, 4);
                p0 += __shfl_xor_sync(0xffffffffu, p0, 8);
                p0 += __shfl_xor_sync(0xffffffffu, p0, 16);
                p1 += __shfl_xor_sync(0xffffffffu, p1, 4);
                p1 += __shfl_xor_sync(0xffffffffu, p1, 8);
                p1 += __shfl_xor_sync(0xffffffffu, p1, 16);
                if (g == 0) {
                    int u0 = nt * 8 + q * 2;
                    sRed[half * 256 + wl * 64 + u0]     = p0;
                    sRed[half * 256 + wl * 64 + u0 + 1] = p1;
                }
            }
            BARH(barid);
            if (t2 < 64) {
                const float* R = sRed + half * 256;
                float sv = R[t2] + R[64 + t2] + R[128 + t2] + R[192 + t2];
                dout[b * 4096 + t2 * 64 + (ba & 63)] = sv + bF;
            }
            BARH(barid);
        }
        o ^= 1;
    }
}

// ---------------- launch -----------------------------------------------------
extern "C" void kernel_launch(void* const* d_in, const int* in_sizes, int n_in,
                              void* d_out, int out_size) {
    (void)in_sizes; (void)n_in; (void)out_size;
    const float* cg      = (const float*)d_in[0];
    const float* phi1_W1 = (const float*)d_in[1];
    const float* phi1_b1 = (const float*)d_in[2];
    const float* phi1_W2 = (const float*)d_in[3];
    const float* phi1_b2 = (const float*)d_in[4];
    const float* phiK_W1 = (const float*)d_in[5];
    const float* phiK_b1 = (const float*)d_in[6];
    const float* phiK_W2 = (const float*)d_in[7];
    const float* phiK_b2 = (const float*)d_in[8];
    const float* g1_W1   = (const float*)d_in[9];
    const float* g1_b1   = (const float*)d_in[10];
    const float* g1_W2   = (const float*)d_in[11];
    const float* g1_b2   = (const float*)d_in[12];
    const float* gK_W1   = (const float*)d_in[13];
    const float* gK_b1   = (const float*)d_in[14];
    const float* gK_W2   = (const float*)d_in[15];
    const float* gK_b2   = (const float*)d_in[16];
    const float* g5_W1   = (const float*)d_in[17];
    const float* g5_b1   = (const float*)d_in[18];
    const float* g5_W2   = (const float*)d_in[19];
    const float* g5_b2   = (const float*)d_in[20];
    float* out = (float*)d_out;

    auto smem_bytes = [](int KB1, bool fin) {
        int S1 = KB1 * 8 + 4;
        int u32s = KB1 * 512 + 4 * 64 * S1 + (fin ? 512 : 2 * 2304) + 16;
        return u32s * 4;
    };
    const int SM1 = smem_bytes(1, false);
    const int SM5 = smem_bytes(5, false);
    const int SM8 = smem_bytes(8, false);
    const int SMF = smem_bytes(8, true);

    cudaFuncSetAttribute(layer_kernel<1, 0, false>, cudaFuncAttributeMaxDynamicSharedMemorySize, SM1);
    cudaFuncSetAttribute(layer_kernel<5, 1, false>, cudaFuncAttributeMaxDynamicSharedMemorySize, SM5);
    cudaFuncSetAttribute(layer_kernel<5, 2, false>, cudaFuncAttributeMaxDynamicSharedMemorySize, SM5);
    cudaFuncSetAttribute(layer_kernel<8, 3, false>, cudaFuncAttributeMaxDynamicSharedMemorySize, SM8);
    cudaFuncSetAttribute(layer_kernel<8, 3, true>,  cudaFuncAttributeMaxDynamicSharedMemorySize, SMF);

    prep_kernel<<<19, 256>>>(phi1_W1, phi1_W2, phiK_W1, phiK_W2, g1_W1, g1_W2, gK_W1, gK_W2, g5_W1);
    cgt_kernel<<<128, 256>>>(cg);

    const int G = 296;

    layer_kernel<1, 0, false><<<G, 256, SM1>>>(phi1_b1, phi1_b2, OFF_PHI1_W1F, OFF_PHI1_W2F, nullptr, nullptr);
    asum_kernel<<<1024, 256>>>();
    pP_kernel<<<128, 256>>>(g1_W1, g1_b1, 65, 1);
    layer_kernel<5, 2, false><<<G, 256, SM5>>>(nullptr, g1_b2, OFF_G1_W1F, OFF_G1_W2F, nullptr, nullptr);

    for (int i = 0; i < 4; ++i) {
        layer_kernel<5, 1, false><<<G, 256, SM5>>>(phiK_b1 + i * 64, phiK_b2 + i * 64,
                                                   OFF_PHIK_W1F + i * 2560, OFF_PHIK_W2F + i * 2048,
                                                   nullptr, nullptr);
        asum_kernel<<<1024, 256>>>();
        if (i < 3) {
            pP_kernel<<<128, 256>>>(gK_W1 + i * 8192, gK_b1 + i * 64, 128, 64);
            layer_kernel<8, 3, false><<<G, 256, SM8>>>(nullptr, gK_b2 + i * 64,
                                                       OFF_GK_W1F + i * 4096, OFF_GK_W2F + i * 2048,
                                                       nullptr, nullptr);
        } else {
            pP_kernel<<<128, 256>>>(g5_W1, g5_b1, 128, 64);
            layer_kernel<8, 3, true><<<G, 256, SMF>>>(nullptr, g5_b2,
                                                      OFF_G5_W1F, 0, g5_W2, out);
        }
    }
}